// round 2
// baseline (speedup 1.0000x reference)
#include <cuda_runtime.h>
#include <cstdint>

// ---------------------------------------------------------------------------
// MoE: out[t,o] = sum_e softmax_e(x@Wg+bg) * gelu(x@We[e]+be[e])
// B*T=16384 tokens, D=256, O=256, E=16.
// Strategy: tf32 mma.sync GEMM, x tile resident in smem, We streamed via
// cp.async from a pre-rounded tf32 scratch copy. fp32 gate/softmax/gelu.
// ---------------------------------------------------------------------------

#define NTOK   16384
#define DD     256
#define OO     256
#define EE     16
#define TILE_M 128
#define TILE_N 128
#define KCH    32
#define NCHUNK (EE * (DD / KCH))   // 128 chunks stream through all experts

#define XS_STRIDE 260              // 260%32==4 -> conflict-free A frag LDS
#define WS_STRIDE 136              // 136%32==8 -> conflict-free B frag LDS
#define GS_STRIDE 17

// shared memory layout (in floats)
#define XS_OFF 0
#define XS_SIZE (TILE_M * XS_STRIDE)            // 33280
#define WS_OFF  (XS_OFF + XS_SIZE)
#define WS_BUF  (KCH * WS_STRIDE)               // 4352
#define WS_SIZE (2 * WS_BUF)                    // 8704
#define GS_OFF  (WS_OFF + WS_SIZE)
#define GS_SIZE (TILE_M * GS_STRIDE)            // 2176
#define BE_OFF  (GS_OFF + GS_SIZE)
#define BE_SIZE (EE * OO)                       // 4096
#define SMEM_FLOATS (BE_OFF + BE_SIZE)          // 48256
#define SMEM_BYTES  (SMEM_FLOATS * 4)           // 193024 B < 227KB

// 4MB scratch: We pre-rounded to tf32 (round-to-nearest) once per launch.
__device__ float g_We_tf32[EE * DD * OO];

__device__ __forceinline__ float tf32_rn(float x) {
    uint32_t u;
    asm("cvt.rna.tf32.f32 %0, %1;" : "=r"(u) : "f"(x));
    return __uint_as_float(u);
}

__device__ __forceinline__ void mma_tf32(float* c, const uint32_t* a,
                                         uint32_t b0, uint32_t b1) {
    asm volatile(
        "mma.sync.aligned.m16n8k8.row.col.f32.tf32.tf32.f32 "
        "{%0,%1,%2,%3}, {%4,%5,%6,%7}, {%8,%9}, {%0,%1,%2,%3};\n"
        : "+f"(c[0]), "+f"(c[1]), "+f"(c[2]), "+f"(c[3])
        : "r"(a[0]), "r"(a[1]), "r"(a[2]), "r"(a[3]), "r"(b0), "r"(b1));
}

__device__ __forceinline__ void cp_async16(uint32_t saddr, const void* gaddr) {
    asm volatile("cp.async.cg.shared.global [%0], [%1], 16;\n"
                 :: "r"(saddr), "l"(gaddr));
}
__device__ __forceinline__ void cp_commit() {
    asm volatile("cp.async.commit_group;\n");
}
template <int N>
__device__ __forceinline__ void cp_wait() {
    asm volatile("cp.async.wait_group %0;\n" :: "n"(N));
}

__device__ __forceinline__ float gelu_exact(float v) {
    return 0.5f * v * (1.0f + erff(v * 0.70710678118654752440f));
}

// ---------------------------------------------------------------------------
// Pre-pass: round We to tf32 (RN) into scratch. ~4MB R + 4MB W, ~1us.
// ---------------------------------------------------------------------------
__global__ void round_we_kernel(const float* __restrict__ We) {
    const float4* src = reinterpret_cast<const float4*>(We);
    float4* dst = reinterpret_cast<float4*>(g_We_tf32);
    int idx = blockIdx.x * blockDim.x + threadIdx.x;
    const int n4 = EE * DD * OO / 4;
    for (int i = idx; i < n4; i += gridDim.x * blockDim.x) {
        float4 v = src[i];
        v.x = tf32_rn(v.x); v.y = tf32_rn(v.y);
        v.z = tf32_rn(v.z); v.w = tf32_rn(v.w);
        dst[i] = v;
    }
}

// ---------------------------------------------------------------------------
// Main fused kernel. One CTA = 128 tokens x 128 output cols, all 16 experts.
// ---------------------------------------------------------------------------
__global__ __launch_bounds__(256, 1)
void moe_kernel(const float* __restrict__ x,
                const float* __restrict__ be,
                const float* __restrict__ Wg,
                const float* __restrict__ bg,
                float* __restrict__ out) {
    extern __shared__ float sm[];
    const int tid  = threadIdx.x;
    const int wid  = tid >> 5;
    const int lane = tid & 31;
    const int gid  = lane >> 2;     // 0..7
    const int tig  = lane & 3;      // 0..3
    const int warpM = wid & 3;      // 4 warps along M
    const int warpN = wid >> 2;     // 2 warps along N
    const int token0 = (blockIdx.x >> 1) * TILE_M;
    const int col0   = (blockIdx.x & 1) * TILE_N;

    // ---- load x tile into smem, rounding to tf32 (RN) -------------------
    {
        const float4* x4 = reinterpret_cast<const float4*>(x + token0 * DD);
        #pragma unroll
        for (int i = 0; i < 32; i++) {
            int idx = tid + (i << 8);          // 0..8191 float4s
            int row = idx >> 6;                // 64 float4 per row
            int cc  = idx & 63;
            float4 v = x4[idx];
            v.x = tf32_rn(v.x); v.y = tf32_rn(v.y);
            v.z = tf32_rn(v.z); v.w = tf32_rn(v.w);
            *reinterpret_cast<float4*>(&sm[XS_OFF + row * XS_STRIDE + cc * 4]) = v;
        }
        const float4* be4 = reinterpret_cast<const float4*>(be);
        #pragma unroll
        for (int i = 0; i < 4; i++) {
            int idx = tid + (i << 8);
            *reinterpret_cast<float4*>(&sm[BE_OFF + idx * 4]) = be4[idx];
        }
    }
    __syncthreads();

    // ---- gate logits: each thread does 1 token x 8 experts --------------
    {
        int t  = tid >> 1;
        int eb = (tid & 1) << 3;   // 0 or 8
        float acc[8];
        #pragma unroll
        for (int j = 0; j < 8; j++) acc[j] = 0.0f;
        const float* xr = &sm[XS_OFF + t * XS_STRIDE];
        const float4* wg4 = reinterpret_cast<const float4*>(Wg);
        #pragma unroll 4
        for (int d = 0; d < DD; d++) {
            float xv = xr[d];
            float4 wA = wg4[d * 4 + (eb >> 2)];
            float4 wB = wg4[d * 4 + (eb >> 2) + 1];
            acc[0] += xv * wA.x; acc[1] += xv * wA.y;
            acc[2] += xv * wA.z; acc[3] += xv * wA.w;
            acc[4] += xv * wB.x; acc[5] += xv * wB.y;
            acc[6] += xv * wB.z; acc[7] += xv * wB.w;
        }
        #pragma unroll
        for (int j = 0; j < 8; j++)
            sm[GS_OFF + t * GS_STRIDE + eb + j] = acc[j] + bg[eb + j];
    }
    __syncthreads();

    // ---- softmax over experts (1 thread per token) ----------------------
    if (tid < TILE_M) {
        float* g = &sm[GS_OFF + tid * GS_STRIDE];
        float m = g[0];
        #pragma unroll
        for (int j = 1; j < EE; j++) m = fmaxf(m, g[j]);
        float s = 0.0f;
        #pragma unroll
        for (int j = 0; j < EE; j++) { float v = __expf(g[j] - m); s += v; g[j] = v; }
        float inv = 1.0f / s;
        #pragma unroll
        for (int j = 0; j < EE; j++) g[j] *= inv;
    }
    __syncthreads();

    // ---- main loop: stream We chunks, tf32 mma, fused epilogue ----------
    float oacc[2][8][4];
    #pragma unroll
    for (int mi = 0; mi < 2; mi++)
        #pragma unroll
        for (int j = 0; j < 8; j++)
            #pragma unroll
            for (int q = 0; q < 4; q++) oacc[mi][j][q] = 0.0f;

    const int rowbase = warpM * 32;
    const int nbase   = warpN * 64;

    const uint32_t ws_smem = (uint32_t)__cvta_generic_to_shared(&sm[WS_OFF]);

    // issue cp.async for chunk c into buffer (c&1): 4x16B per thread
    auto issue_chunk = [&](int c) {
        const float* gsrc = g_We_tf32 + c * KCH * OO + col0;
        uint32_t sdst = ws_smem + (uint32_t)(c & 1) * (WS_BUF * 4);
        #pragma unroll
        for (int i = 0; i < 4; i++) {
            int idx = tid + (i << 8);       // 0..1023
            int k   = idx >> 5;             // 0..31
            int n4  = (idx & 31) << 2;      // 0..124
            cp_async16(sdst + (uint32_t)(k * WS_STRIDE + n4) * 4,
                       gsrc + k * OO + n4);
        }
        cp_commit();
    };

    issue_chunk(0);

    const float* xsA0 = &sm[XS_OFF + (rowbase + gid) * XS_STRIDE + tig];
    const float* xsA1 = xsA0 + 16 * XS_STRIDE;

    #pragma unroll 1
    for (int e = 0; e < EE; e++) {
        float hacc[2][8][4];
        #pragma unroll
        for (int mi = 0; mi < 2; mi++)
            #pragma unroll
            for (int j = 0; j < 8; j++)
                #pragma unroll
                for (int q = 0; q < 4; q++) hacc[mi][j][q] = 0.0f;

        #pragma unroll 1
        for (int kc = 0; kc < 8; kc++) {
            int c = e * 8 + kc;
            if (c + 1 < NCHUNK) { issue_chunk(c + 1); cp_wait<1>(); }
            else                { cp_wait<0>(); }
            __syncthreads();

            const float* wsb = &sm[WS_OFF + (c & 1) * WS_BUF
                                   + tig * WS_STRIDE + nbase + gid];
            const float* xA0 = xsA0 + kc * KCH;
            const float* xA1 = xsA1 + kc * KCH;

            #pragma unroll
            for (int ks = 0; ks < 4; ks++) {
                const int k = ks * 8;
                uint32_t a0[4], a1[4];
                a0[0] = __float_as_uint(xA0[k]);
                a0[1] = __float_as_uint(xA0[8 * XS_STRIDE + k]);
                a0[2] = __float_as_uint(xA0[k + 4]);
                a0[3] = __float_as_uint(xA0[8 * XS_STRIDE + k + 4]);
                a1[0] = __float_as_uint(xA1[k]);
                a1[1] = __float_as_uint(xA1[8 * XS_STRIDE + k]);
                a1[2] = __float_as_uint(xA1[k + 4]);
                a1[3] = __float_as_uint(xA1[8 * XS_STRIDE + k + 4]);
                const float* wk = wsb + ks * 8 * WS_STRIDE;
                #pragma unroll
                for (int j = 0; j < 8; j++) {
                    uint32_t b0 = __float_as_uint(wk[j * 8]);
                    uint32_t b1 = __float_as_uint(wk[4 * WS_STRIDE + j * 8]);
                    mma_tf32(hacc[0][j], a0, b0, b1);
                    mma_tf32(hacc[1][j], a1, b0, b1);
                }
            }
            __syncthreads();
        }

        // epilogue for expert e: bias + exact gelu + gate-weighted accumulate
        #pragma unroll
        for (int mi = 0; mi < 2; mi++) {
            int r = rowbase + mi * 16 + gid;
            float g0 = sm[GS_OFF + r * GS_STRIDE + e];
            float g1 = sm[GS_OFF + (r + 8) * GS_STRIDE + e];
            #pragma unroll
            for (int j = 0; j < 8; j++) {
                int n = nbase + j * 8 + 2 * tig;
                float b0 = sm[BE_OFF + e * OO + col0 + n];
                float b1 = sm[BE_OFF + e * OO + col0 + n + 1];
                float v;
                v = hacc[mi][j][0] + b0; oacc[mi][j][0] += g0 * gelu_exact(v);
                v = hacc[mi][j][1] + b1; oacc[mi][j][1] += g0 * gelu_exact(v);
                v = hacc[mi][j][2] + b0; oacc[mi][j][2] += g1 * gelu_exact(v);
                v = hacc[mi][j][3] + b1; oacc[mi][j][3] += g1 * gelu_exact(v);
            }
        }
    }

    // ---- store output ----------------------------------------------------
    #pragma unroll
    for (int mi = 0; mi < 2; mi++) {
        int r0 = token0 + rowbase + mi * 16 + gid;
        #pragma unroll
        for (int j = 0; j < 8; j++) {
            int n = col0 + nbase + j * 8 + 2 * tig;
            float2 v0 = make_float2(oacc[mi][j][0], oacc[mi][j][1]);
            float2 v1 = make_float2(oacc[mi][j][2], oacc[mi][j][3]);
            *reinterpret_cast<float2*>(&out[(size_t)r0 * OO + n]) = v0;
            *reinterpret_cast<float2*>(&out[(size_t)(r0 + 8) * OO + n]) = v1;
        }
    }
}

// ---------------------------------------------------------------------------
// kernel_launch: graph-capturable, allocation-free.
// Inputs (metadata order): x[4,4096,256] f32, We[16,256,256] f32,
// be[16,256] f32, Wg[256,16] f32, bg[16] f32. Output: [4,4096,256] f32.
// ---------------------------------------------------------------------------
extern "C" void kernel_launch(void* const* d_in, const int* in_sizes, int n_in,
                              void* d_out, int out_size) {
    const float* x  = (const float*)d_in[0];
    const float* We = (const float*)d_in[1];
    const float* be = (const float*)d_in[2];
    const float* Wg = (const float*)d_in[3];
    const float* bg = (const float*)d_in[4];
    float* out = (float*)d_out;

    cudaFuncSetAttribute(moe_kernel,
                         cudaFuncAttributeMaxDynamicSharedMemorySize,
                         SMEM_BYTES);

    round_we_kernel<<<256, 256>>>(We);
    moe_kernel<<<NTOK / TILE_M * 2, 256, SMEM_BYTES>>>(x, be, Wg, bg, out);
}

// round 5
// speedup vs baseline: 1.0907x; 1.0907x over previous
#include <cuda_runtime.h>
#include <cstdint>

// ---------------------------------------------------------------------------
// MoE, sm_103 (no tcgen05 in this toolchain): tf32 mma.sync, fragment-order
// smem layouts, 2 CTAs/SM.
//   out[t,o] = sum_e softmax_e(x@Wg+bg)_e * gelu(x@We[e] + be[e])
// B*T=16384, D=256, O=256, E=16.
//
// moe_kernel: CTA = 64 tokens x 128 cols, all 16 experts.
//   8 warps = 2(M) x 4(N); warp tile 32x32; mma.m16n8k8.tf32.
//   A (x) pre-permuted into smem in fragment order (built in prologue).
//   B (We) pre-permuted in gmem (permute_we) -> cp.async identity copy,
//   2-buffer ring. All mainloop LDS are conflict-free LDS.128.
// ---------------------------------------------------------------------------

#define NTOK   16384
#define DD     256
#define OO     256
#define EE     16
#define TILE_M 64
#define TILE_N 128
#define NTHREADS 256

// smem layout (bytes)
#define SM_A      0                      // [wm2][kc8][ks4][mi2][lane32][16B]
#define SM_A_SIZE 65536
#define SM_B      65536                  // 2 x 16KB ring
#define SM_B_BUF  16384
#define SM_GS     (SM_B + 2 * SM_B_BUF)  // 64*17 floats = 4352 B
#define SM_BE     (SM_GS + 4352)         // 16*128 floats = 8192 B
#define SMEM_TOTAL (SM_BE + 8192)        // 110848 B -> 2 CTAs/SM

// scratch: We in mma-fragment order, tf32-rounded.
// [e][ct2][kc8][wn4][ks4][p2][lane32][4 floats]
__device__ float g_WeB[EE * DD * OO];
__device__ float g_gate[NTOK * EE];

// ---------------------------------------------------------------------------
__device__ __forceinline__ float tf32_rn(float x) {
    uint32_t u;
    asm("cvt.rna.tf32.f32 %0, %1;" : "=r"(u) : "f"(x));
    return __uint_as_float(u);
}
__device__ __forceinline__ uint32_t smem_u32(const void* p) {
    uint32_t a;
    asm("{ .reg .u64 t; cvta.to.shared.u64 t, %1; cvt.u32.u64 %0, t; }"
        : "=r"(a) : "l"(p));
    return a;
}
__device__ __forceinline__ void mma_tf32(float* c, const float4& a,
                                         float b0, float b1) {
    asm volatile(
        "mma.sync.aligned.m16n8k8.row.col.f32.tf32.tf32.f32 "
        "{%0,%1,%2,%3}, {%4,%5,%6,%7}, {%8,%9}, {%0,%1,%2,%3};\n"
        : "+f"(c[0]), "+f"(c[1]), "+f"(c[2]), "+f"(c[3])
        : "r"(__float_as_uint(a.x)), "r"(__float_as_uint(a.y)),
          "r"(__float_as_uint(a.z)), "r"(__float_as_uint(a.w)),
          "r"(__float_as_uint(b0)), "r"(__float_as_uint(b1)));
}
__device__ __forceinline__ void cp_async16(uint32_t saddr, const void* gaddr) {
    asm volatile("cp.async.cg.shared.global [%0], [%1], 16;\n"
                 :: "r"(saddr), "l"(gaddr));
}
__device__ __forceinline__ void cp_commit() {
    asm volatile("cp.async.commit_group;\n");
}
template <int N>
__device__ __forceinline__ void cp_wait() {
    asm volatile("cp.async.wait_group %0;\n" :: "n"(N));
}
__device__ __forceinline__ float gelu_exact(float v) {
    return 0.5f * v * (1.0f + erff(v * 0.70710678118654752440f));
}

// ---------------------------------------------------------------------------
// Pre-pass: permute We[e][d][o] into fragment order g_WeB, tf32-rounded.
// One thread per float4 group. idx bits: e(4)|ct(1)|kc(3)|wn(2)|ks(2)|p(1)|lane(5)
// ---------------------------------------------------------------------------
__global__ void permute_we(const float* __restrict__ We) {
    int idx = blockIdx.x * blockDim.x + threadIdx.x;   // 0 .. 262143
    int lane = idx & 31;
    int p    = (idx >> 5) & 1;
    int ks   = (idx >> 6) & 3;
    int wn   = (idx >> 8) & 3;
    int kc   = (idx >> 10) & 7;
    int ct   = (idx >> 13) & 1;
    int e    = idx >> 14;
    int d0 = kc * 32 + ks * 8 + (lane & 3);
    int o0 = ct * 128 + wn * 32 + (lane >> 2) + p * 16;
    const float* w = We + (size_t)e * DD * OO;
    float4 v;
    v.x = tf32_rn(w[(size_t)d0 * OO + o0]);            // j b0
    v.y = tf32_rn(w[(size_t)(d0 + 4) * OO + o0]);      // j b1
    v.z = tf32_rn(w[(size_t)d0 * OO + o0 + 8]);        // j+1 b0
    v.w = tf32_rn(w[(size_t)(d0 + 4) * OO + o0 + 8]);  // j+1 b1
    *reinterpret_cast<float4*>(g_WeB + (size_t)idx * 4) = v;
}

// ---------------------------------------------------------------------------
// Gate: softmax(x@Wg + bg) -> g_gate. fp32. One block = 128 tokens.
// ---------------------------------------------------------------------------
#define GK_SMEM ((128 * 260 + 128 * 17) * 4)
__global__ __launch_bounds__(256, 1)
void gate_kernel(const float* __restrict__ x, const float* __restrict__ Wg,
                 const float* __restrict__ bg) {
    extern __shared__ float sm[];
    const int tid = threadIdx.x;
    const int token0 = blockIdx.x * 128;
    const float4* x4 = reinterpret_cast<const float4*>(x + (size_t)token0 * DD);
    #pragma unroll
    for (int i = 0; i < 32; i++) {
        int idx = tid + (i << 8);
        int row = idx >> 6, cc = idx & 63;
        *reinterpret_cast<float4*>(&sm[row * 260 + cc * 4]) = x4[idx];
    }
    __syncthreads();
    {
        int t = tid >> 1, eb = (tid & 1) << 3;
        float acc[8];
        #pragma unroll
        for (int j = 0; j < 8; j++) acc[j] = 0.0f;
        const float* xr = &sm[t * 260];
        const float4* wg4 = reinterpret_cast<const float4*>(Wg);
        #pragma unroll 4
        for (int d = 0; d < DD; d++) {
            float xv = xr[d];
            float4 wA = wg4[d * 4 + (eb >> 2)];
            float4 wB = wg4[d * 4 + (eb >> 2) + 1];
            acc[0] += xv * wA.x; acc[1] += xv * wA.y;
            acc[2] += xv * wA.z; acc[3] += xv * wA.w;
            acc[4] += xv * wB.x; acc[5] += xv * wB.y;
            acc[6] += xv * wB.z; acc[7] += xv * wB.w;
        }
        #pragma unroll
        for (int j = 0; j < 8; j++)
            sm[128 * 260 + t * 17 + eb + j] = acc[j] + bg[eb + j];
    }
    __syncthreads();
    if (tid < 128) {
        float* g = &sm[128 * 260 + tid * 17];
        float m = g[0];
        #pragma unroll
        for (int j = 1; j < EE; j++) m = fmaxf(m, g[j]);
        float s = 0.0f;
        float v[EE];
        #pragma unroll
        for (int j = 0; j < EE; j++) { v[j] = __expf(g[j] - m); s += v[j]; }
        float inv = 1.0f / s;
        #pragma unroll
        for (int j = 0; j < EE; j++)
            g_gate[(size_t)(token0 + tid) * EE + j] = v[j] * inv;
    }
}

// ---------------------------------------------------------------------------
// Main kernel.
// ---------------------------------------------------------------------------
__global__ __launch_bounds__(NTHREADS, 2)
void moe_kernel(const float* __restrict__ x, const float* __restrict__ be,
                float* __restrict__ out) {
    extern __shared__ float smf[];
    char* smc = reinterpret_cast<char*>(smf);
    const int tid  = threadIdx.x;
    const int wid  = tid >> 5;
    const int lane = tid & 31;
    const int wm = wid & 1;          // 2 row groups of 32 tokens
    const int wn = wid >> 1;         // 4 col groups of 32 cols
    const int token0 = (blockIdx.x >> 1) * TILE_M;
    const int ct     = blockIdx.x & 1;
    const int col0   = ct * TILE_N;

    const uint32_t sb_B = smem_u32(smc + SM_B);

    // issue cp.async for chunk c2 into ring buffer (c2&1): contiguous 16KB.
    auto issue = [&](int c2) {
        int e2 = c2 >> 3, kc2 = c2 & 7;
        const float* src = g_WeB + (size_t)(e2 * 16 + ct * 8 + kc2) * 4096
                         + tid * 4;
        uint32_t dst = sb_B + (uint32_t)(c2 & 1) * SM_B_BUF + (uint32_t)tid * 16;
        #pragma unroll
        for (int i = 0; i < 4; i++)
            cp_async16(dst + i * 4096, src + i * 1024);
        cp_commit();
    };

    issue(0);
    issue(1);

    // ---- prologue: build A_perm (fragment-order x, tf32), bias, gate ----
    {
        #pragma unroll
        for (int it = 0; it < 16; it++) {
            int idx = tid + (it << 8);         // 0..4095 float4 slots
            int ln = idx & 31;
            int mi = (idx >> 5) & 1;
            int ks = (idx >> 6) & 3;
            int kc = (idx >> 8) & 7;
            int wmm = idx >> 11;
            int r = ln >> 2, cc = ln & 3;
            int row = token0 + wmm * 32 + mi * 16 + r;
            int d = kc * 32 + ks * 8 + cc;
            const float* xp = x + (size_t)row * DD + d;
            float4 v;
            v.x = tf32_rn(xp[0]);
            v.y = tf32_rn(xp[8 * DD]);
            v.z = tf32_rn(xp[4]);
            v.w = tf32_rn(xp[8 * DD + 4]);
            *reinterpret_cast<float4*>(smc + SM_A + (size_t)idx * 16) = v;
        }
        // bias slice be[e][col0..col0+128)
        #pragma unroll
        for (int it = 0; it < 2; it++) {
            int idx = tid + (it << 8);         // 0..511 float4s
            int e = idx >> 5, f4 = idx & 31;
            float4 v = *reinterpret_cast<const float4*>(
                be + (size_t)e * OO + col0 + f4 * 4);
            *reinterpret_cast<float4*>(smc + SM_BE + ((size_t)e * 128 + f4 * 4) * 4) = v;
        }
        // gate rows token0..+63 -> stride-17
        float* gsm = reinterpret_cast<float*>(smc + SM_GS);
        #pragma unroll
        for (int it = 0; it < 4; it++) {
            int idx = tid + (it << 8);         // 0..1023
            int t = idx >> 4, e = idx & 15;
            gsm[t * 17 + e] = g_gate[(size_t)(token0 + t) * EE + e];
        }
    }

    float oacc[2][4][4];
    #pragma unroll
    for (int mi = 0; mi < 2; mi++)
        #pragma unroll
        for (int j = 0; j < 4; j++)
            #pragma unroll
            for (int q = 0; q < 4; q++) oacc[mi][j][q] = 0.0f;

    const float* gsm  = reinterpret_cast<const float*>(smc + SM_GS);
    const float* besm = reinterpret_cast<const float*>(smc + SM_BE);

    // ---- mainloop over experts / K-chunks ----
    #pragma unroll 1
    for (int e = 0; e < EE; e++) {
        float hacc[2][4][4];
        #pragma unroll
        for (int mi = 0; mi < 2; mi++)
            #pragma unroll
            for (int j = 0; j < 4; j++)
                #pragma unroll
                for (int q = 0; q < 4; q++) hacc[mi][j][q] = 0.0f;

        #pragma unroll 1
        for (int kc = 0; kc < 8; kc++) {
            const int c = e * 8 + kc;
            if (c >= 126) cp_wait<0>(); else cp_wait<1>();
            __syncthreads();

            const char* bb = smc + SM_B + (c & 1) * SM_B_BUF;
            const char* ab = smc + SM_A + ((wm * 8 + kc) * 4) * 1024;
            #pragma unroll
            for (int ks = 0; ks < 4; ks++) {
                float4 a0 = *reinterpret_cast<const float4*>(
                    ab + ks * 1024 + lane * 16);
                float4 a1 = *reinterpret_cast<const float4*>(
                    ab + ks * 1024 + 512 + lane * 16);
                float4 bl = *reinterpret_cast<const float4*>(
                    bb + ((wn * 4 + ks) * 2) * 512 + lane * 16);
                float4 bh = *reinterpret_cast<const float4*>(
                    bb + ((wn * 4 + ks) * 2 + 1) * 512 + lane * 16);
                mma_tf32(hacc[0][0], a0, bl.x, bl.y);
                mma_tf32(hacc[1][0], a1, bl.x, bl.y);
                mma_tf32(hacc[0][1], a0, bl.z, bl.w);
                mma_tf32(hacc[1][1], a1, bl.z, bl.w);
                mma_tf32(hacc[0][2], a0, bh.x, bh.y);
                mma_tf32(hacc[1][2], a1, bh.x, bh.y);
                mma_tf32(hacc[0][3], a0, bh.z, bh.w);
                mma_tf32(hacc[1][3], a1, bh.z, bh.w);
            }
            __syncthreads();
            if (c + 2 < EE * 8) issue(c + 2);
        }

        // epilogue: bias + exact gelu + gate-weighted accumulate
        #pragma unroll
        for (int mi = 0; mi < 2; mi++) {
            int rr = wm * 32 + mi * 16 + (lane >> 2);
            float g0 = gsm[rr * 17 + e];
            float g1 = gsm[(rr + 8) * 17 + e];
            #pragma unroll
            for (int j = 0; j < 4; j++) {
                int n0 = wn * 32 + j * 8 + (lane & 3) * 2;
                float bv0 = besm[e * 128 + n0];
                float bv1 = besm[e * 128 + n0 + 1];
                oacc[mi][j][0] = fmaf(g0, gelu_exact(hacc[mi][j][0] + bv0), oacc[mi][j][0]);
                oacc[mi][j][1] = fmaf(g0, gelu_exact(hacc[mi][j][1] + bv1), oacc[mi][j][1]);
                oacc[mi][j][2] = fmaf(g1, gelu_exact(hacc[mi][j][2] + bv0), oacc[mi][j][2]);
                oacc[mi][j][3] = fmaf(g1, gelu_exact(hacc[mi][j][3] + bv1), oacc[mi][j][3]);
            }
        }
    }

    // ---- store ----
    #pragma unroll
    for (int mi = 0; mi < 2; mi++) {
        int row = token0 + wm * 32 + mi * 16 + (lane >> 2);
        #pragma unroll
        for (int j = 0; j < 4; j++) {
            int n = col0 + wn * 32 + j * 8 + (lane & 3) * 2;
            float2 v0 = make_float2(oacc[mi][j][0], oacc[mi][j][1]);
            float2 v1 = make_float2(oacc[mi][j][2], oacc[mi][j][3]);
            *reinterpret_cast<float2*>(out + (size_t)row * OO + n) = v0;
            *reinterpret_cast<float2*>(out + (size_t)(row + 8) * OO + n) = v1;
        }
    }
}

// ---------------------------------------------------------------------------
// kernel_launch — graph-capturable, allocation-free.
// Inputs: x[4,4096,256] f32, We[16,256,256] f32, be[16,256] f32,
//         Wg[256,16] f32, bg[16] f32. Output: [4,4096,256] f32.
// ---------------------------------------------------------------------------
extern "C" void kernel_launch(void* const* d_in, const int* in_sizes, int n_in,
                              void* d_out, int out_size) {
    const float* x  = (const float*)d_in[0];
    const float* We = (const float*)d_in[1];
    const float* be = (const float*)d_in[2];
    const float* Wg = (const float*)d_in[3];
    const float* bg = (const float*)d_in[4];
    float* out = (float*)d_out;

    cudaFuncSetAttribute(gate_kernel,
                         cudaFuncAttributeMaxDynamicSharedMemorySize, GK_SMEM);
    cudaFuncSetAttribute(moe_kernel,
                         cudaFuncAttributeMaxDynamicSharedMemorySize, SMEM_TOTAL);

    permute_we<<<1024, 256>>>(We);
    gate_kernel<<<NTOK / 128, 256, GK_SMEM>>>(x, Wg, bg);
    moe_kernel<<<(NTOK / TILE_M) * 2, NTHREADS, SMEM_TOTAL>>>(x, be, out);
}

// round 6
// speedup vs baseline: 1.1073x; 1.0152x over previous
#include <cuda_runtime.h>
#include <cstdint>

// ---------------------------------------------------------------------------
// MoE, sm_103: tf32 mma.sync + producer/consumer warp specialization.
//   out[t,o] = sum_e softmax_e(x@Wg+bg)_e * gelu(x@We[e] + be[e])
// B*T=16384, D=256, O=256, E=16.
//
// moe_kernel: CTA = 64 tokens x 128 cols, all 16 experts. 9 warps:
//   warps 0-7 compute (2Mx4N, warp tile 32x32, mma.m16n8k8.tf32),
//   warp 8 producer (cp.async streams We chunks into a 3-stage mbarrier ring).
//   NO __syncthreads in the mainloop. Gate softmax fused into the prologue.
// ---------------------------------------------------------------------------

#define NTOK   16384
#define DD     256
#define OO     256
#define EE     16
#define TILE_M 64
#define TILE_N 128
#define NTHREADS 288          // 8 compute warps + 1 producer warp
#define NBUF   3

// smem layout (bytes)
#define SM_A      0                      // [wm2][kc8][ks4][mi2][lane32][16B]
#define SM_A_SIZE 65536
#define SM_B      65536                  // 3 x 16KB ring
#define SM_B_BUF  16384
#define SM_BAR    (SM_B + NBUF * SM_B_BUF)   // 6 mbarriers
#define MB_FULL(i)  (SM_BAR + (i) * 8)
#define MB_EMPTY(i) (SM_BAR + 24 + (i) * 8)
#define SMEM_TOTAL  (SM_BAR + 64)        // 114752 B -> 2 CTAs/SM

// scratch: We in mma-fragment order, tf32-rounded.
// [e][ct2][kc8][wn4][ks4][p2][lane32][4 floats]
__device__ float g_WeB[EE * DD * OO];
__device__ float g_gate[NTOK * EE];

// ---------------------------------------------------------------------------
__device__ __forceinline__ float tf32_rn(float x) {
    uint32_t u;
    asm("cvt.rna.tf32.f32 %0, %1;" : "=r"(u) : "f"(x));
    return __uint_as_float(u);
}
__device__ __forceinline__ uint32_t smem_u32(const void* p) {
    uint32_t a;
    asm("{ .reg .u64 t; cvta.to.shared.u64 t, %1; cvt.u32.u64 %0, t; }"
        : "=r"(a) : "l"(p));
    return a;
}
__device__ __forceinline__ void mma_tf32(float* c, const float4& a,
                                         float b0, float b1) {
    asm volatile(
        "mma.sync.aligned.m16n8k8.row.col.f32.tf32.tf32.f32 "
        "{%0,%1,%2,%3}, {%4,%5,%6,%7}, {%8,%9}, {%0,%1,%2,%3};\n"
        : "+f"(c[0]), "+f"(c[1]), "+f"(c[2]), "+f"(c[3])
        : "r"(__float_as_uint(a.x)), "r"(__float_as_uint(a.y)),
          "r"(__float_as_uint(a.z)), "r"(__float_as_uint(a.w)),
          "r"(__float_as_uint(b0)), "r"(__float_as_uint(b1)));
}
__device__ __forceinline__ void cp_async16(uint32_t saddr, const void* gaddr) {
    asm volatile("cp.async.cg.shared.global [%0], [%1], 16;\n"
                 :: "r"(saddr), "l"(gaddr));
}
__device__ __forceinline__ float gelu_exact(float v) {
    return 0.5f * v * (1.0f + erff(v * 0.70710678118654752440f));
}

#define MBAR_INIT(a, n) \
    asm volatile("mbarrier.init.shared.b64 [%0], %1;" :: "r"(a), "r"((uint32_t)(n)) : "memory")
#define MBAR_ARRIVE(a) \
    asm volatile("mbarrier.arrive.shared.b64 _, [%0];" :: "r"(a) : "memory")
#define MBAR_WAIT(a, ph) do {                                                 \
    asm volatile("{\n\t.reg .pred P1;\n\t"                                    \
        "WL_%=:\n\tmbarrier.try_wait.parity.acquire.cta.shared::cta.b64 P1, [%0], %1, 0x989680;\n\t" \
        "@P1 bra.uni WD_%=;\n\tbra.uni WL_%=;\n\tWD_%=:\n\t}"                 \
        :: "r"(a), "r"((uint32_t)(ph)) : "memory");                           \
} while (0)
#define CP_ARRIVE_NOINC(a) \
    asm volatile("cp.async.mbarrier.arrive.noinc.shared::cta.b64 [%0];" :: "r"(a) : "memory")
#define NAMED_BAR(id, n) \
    asm volatile("bar.sync %0, %1;" :: "r"(id), "r"(n) : "memory")

// ---------------------------------------------------------------------------
// Pre-pass: permute We[e][d][o] into fragment order g_WeB, tf32-rounded.
// idx bits: e(4)|ct(1)|kc(3)|wn(2)|ks(2)|p(1)|lane(5)
// ---------------------------------------------------------------------------
__global__ void permute_we(const float* __restrict__ We) {
    int idx = blockIdx.x * blockDim.x + threadIdx.x;   // 0 .. 262143
    int lane = idx & 31;
    int p    = (idx >> 5) & 1;
    int ks   = (idx >> 6) & 3;
    int wn   = (idx >> 8) & 3;
    int kc   = (idx >> 10) & 7;
    int ct   = (idx >> 13) & 1;
    int e    = idx >> 14;
    int d0 = kc * 32 + ks * 8 + (lane & 3);
    int o0 = ct * 128 + wn * 32 + (lane >> 2) + p * 16;
    const float* w = We + (size_t)e * DD * OO;
    float4 v;
    v.x = tf32_rn(w[(size_t)d0 * OO + o0]);
    v.y = tf32_rn(w[(size_t)(d0 + 4) * OO + o0]);
    v.z = tf32_rn(w[(size_t)d0 * OO + o0 + 8]);
    v.w = tf32_rn(w[(size_t)(d0 + 4) * OO + o0 + 8]);
    *reinterpret_cast<float4*>(g_WeB + (size_t)idx * 4) = v;
}

// ---------------------------------------------------------------------------
// Main kernel.
// ---------------------------------------------------------------------------
__global__ __launch_bounds__(NTHREADS, 2)
void moe_kernel(const float* __restrict__ x, const float* __restrict__ be,
                const float* __restrict__ Wg, const float* __restrict__ bg,
                float* __restrict__ out) {
    extern __shared__ float smf[];
    char* smc = reinterpret_cast<char*>(smf);
    const uint32_t sbase = smem_u32(smc);
    const int tid  = threadIdx.x;
    const int wid  = tid >> 5;
    const int lane = tid & 31;
    const int token0 = (blockIdx.x >> 1) * TILE_M;
    const int ct     = blockIdx.x & 1;
    const int col0   = ct * TILE_N;

    if (tid == 0) {
        #pragma unroll
        for (int i = 0; i < NBUF; i++) {
            MBAR_INIT(sbase + MB_FULL(i), 32);   // producer threads, noinc
            MBAR_INIT(sbase + MB_EMPTY(i), 8);   // one arrive per compute warp
        }
    }
    __syncthreads();

    if (wid == 8) {
        // ================= producer warp =================
        int ph_e[NBUF];
        #pragma unroll
        for (int i = 0; i < NBUF; i++) ph_e[i] = 0;
        int buf = 0;
        #pragma unroll 1
        for (int c = 0; c < EE * 8; c++) {
            if (c >= NBUF) { MBAR_WAIT(sbase + MB_EMPTY(buf), ph_e[buf]); }
            if (c >= NBUF && buf == NBUF - 1) {
                ph_e[0] ^= 1; ph_e[1] ^= 1; ph_e[2] ^= 1;
            }
            const int e = c >> 3, kc = c & 7;
            const char* gsrc = reinterpret_cast<const char*>(
                g_WeB + (size_t)(e * 16 + ct * 8 + kc) * 4096) + lane * 16;
            const uint32_t dst = sbase + SM_B + (uint32_t)buf * SM_B_BUF
                               + (uint32_t)lane * 16;
            #pragma unroll
            for (int i = 0; i < 32; i++)
                cp_async16(dst + i * 512, gsrc + i * 512);
            CP_ARRIVE_NOINC(sbase + MB_FULL(buf));
            buf = (buf == NBUF - 1) ? 0 : buf + 1;
        }
    } else {
        // ================= compute warps =================
        const int wm = wid & 1;          // 2 row groups of 32 tokens
        const int wn = wid >> 1;         // 4 col groups of 32 cols

        // ---- build A_perm (fragment-order x, tf32) -------------------
        {
            #pragma unroll
            for (int it = 0; it < 16; it++) {
                int idx = tid + (it << 8);         // 0..4095 float4 slots
                int ln = idx & 31;
                int mi = (idx >> 5) & 1;
                int ks = (idx >> 6) & 3;
                int kc = (idx >> 8) & 7;
                int wmm = idx >> 11;
                int r = ln >> 2, cc = ln & 3;
                int row = token0 + wmm * 32 + mi * 16 + r;
                int d = kc * 32 + ks * 8 + cc;
                const float* xp = x + (size_t)row * DD + d;
                float4 v;
                v.x = tf32_rn(xp[0]);
                v.y = tf32_rn(xp[8 * DD]);
                v.z = tf32_rn(xp[4]);
                v.w = tf32_rn(xp[8 * DD + 4]);
                *reinterpret_cast<float4*>(smc + SM_A + (size_t)idx * 16) = v;
            }
        }
        // ---- gate: softmax(x@Wg+bg) for our 64 tokens ----------------
        // thread: token = tid>>2, experts 4q..4q+3 (q = tid&3)
        {
            const int tok = tid >> 2;
            const int q   = tid & 3;
            float acc0 = 0.f, acc1 = 0.f, acc2 = 0.f, acc3 = 0.f;
            const float4* x4 = reinterpret_cast<const float4*>(
                x + (size_t)(token0 + tok) * DD);
            const float4* wg4 = reinterpret_cast<const float4*>(Wg);
            #pragma unroll 4
            for (int d4 = 0; d4 < 64; d4++) {
                float4 xv = x4[d4];
                float4 w0 = wg4[(d4 * 4 + 0) * 4 + q];
                float4 w1 = wg4[(d4 * 4 + 1) * 4 + q];
                float4 w2 = wg4[(d4 * 4 + 2) * 4 + q];
                float4 w3 = wg4[(d4 * 4 + 3) * 4 + q];
                acc0 += xv.x * w0.x + xv.y * w1.x + xv.z * w2.x + xv.w * w3.x;
                acc1 += xv.x * w0.y + xv.y * w1.y + xv.z * w2.y + xv.w * w3.y;
                acc2 += xv.x * w0.z + xv.y * w1.z + xv.z * w2.z + xv.w * w3.z;
                acc3 += xv.x * w0.w + xv.y * w1.w + xv.z * w2.w + xv.w * w3.w;
            }
            acc0 += __ldg(bg + q * 4 + 0);
            acc1 += __ldg(bg + q * 4 + 1);
            acc2 += __ldg(bg + q * 4 + 2);
            acc3 += __ldg(bg + q * 4 + 3);
            float m = fmaxf(fmaxf(acc0, acc1), fmaxf(acc2, acc3));
            m = fmaxf(m, __shfl_xor_sync(0xFFFFFFFFu, m, 1));
            m = fmaxf(m, __shfl_xor_sync(0xFFFFFFFFu, m, 2));
            float v0 = __expf(acc0 - m), v1 = __expf(acc1 - m);
            float v2 = __expf(acc2 - m), v3 = __expf(acc3 - m);
            float s = v0 + v1 + v2 + v3;
            s += __shfl_xor_sync(0xFFFFFFFFu, s, 1);
            s += __shfl_xor_sync(0xFFFFFFFFu, s, 2);
            float inv = 1.0f / s;
            float4 g = make_float4(v0 * inv, v1 * inv, v2 * inv, v3 * inv);
            *reinterpret_cast<float4*>(
                g_gate + (size_t)(token0 + tok) * EE + q * 4) = g;
        }
        NAMED_BAR(1, 256);     // compute warps only: A + gate ready

        float oacc[2][4][4];
        #pragma unroll
        for (int mi = 0; mi < 2; mi++)
            #pragma unroll
            for (int j = 0; j < 4; j++)
                #pragma unroll
                for (int q = 0; q < 4; q++) oacc[mi][j][q] = 0.0f;

        int ph_f[NBUF];
        #pragma unroll
        for (int i = 0; i < NBUF; i++) ph_f[i] = 0;
        int buf = 0;

        #pragma unroll 1
        for (int e = 0; e < EE; e++) {
            float hacc[2][4][4];
            #pragma unroll
            for (int mi = 0; mi < 2; mi++)
                #pragma unroll
                for (int j = 0; j < 4; j++)
                    #pragma unroll
                    for (int q = 0; q < 4; q++) hacc[mi][j][q] = 0.0f;

            #pragma unroll 1
            for (int kc = 0; kc < 8; kc++) {
                MBAR_WAIT(sbase + MB_FULL(buf), ph_f[buf]);
                ph_f[buf] ^= 1;

                const char* bb = smc + SM_B + buf * SM_B_BUF;
                const char* ab = smc + SM_A + ((wm * 8 + kc) * 4) * 1024;
                #pragma unroll
                for (int ks = 0; ks < 4; ks++) {
                    float4 a0 = *reinterpret_cast<const float4*>(
                        ab + ks * 1024 + lane * 16);
                    float4 a1 = *reinterpret_cast<const float4*>(
                        ab + ks * 1024 + 512 + lane * 16);
                    float4 bl = *reinterpret_cast<const float4*>(
                        bb + ((wn * 4 + ks) * 2) * 512 + lane * 16);
                    float4 bh = *reinterpret_cast<const float4*>(
                        bb + ((wn * 4 + ks) * 2 + 1) * 512 + lane * 16);
                    mma_tf32(hacc[0][0], a0, bl.x, bl.y);
                    mma_tf32(hacc[1][0], a1, bl.x, bl.y);
                    mma_tf32(hacc[0][1], a0, bl.z, bl.w);
                    mma_tf32(hacc[1][1], a1, bl.z, bl.w);
                    mma_tf32(hacc[0][2], a0, bh.x, bh.y);
                    mma_tf32(hacc[1][2], a1, bh.x, bh.y);
                    mma_tf32(hacc[0][3], a0, bh.z, bh.w);
                    mma_tf32(hacc[1][3], a1, bh.z, bh.w);
                }
                if (lane == 0) MBAR_ARRIVE(sbase + MB_EMPTY(buf));
                buf = (buf == NBUF - 1) ? 0 : buf + 1;
            }

            // epilogue: bias + exact gelu + gate-weighted accumulate
            #pragma unroll
            for (int mi = 0; mi < 2; mi++) {
                int rr = token0 + wm * 32 + mi * 16 + (lane >> 2);
                float g0 = __ldg(g_gate + (size_t)rr * EE + e);
                float g1 = __ldg(g_gate + (size_t)(rr + 8) * EE + e);
                #pragma unroll
                for (int j = 0; j < 4; j++) {
                    int n0 = col0 + wn * 32 + j * 8 + (lane & 3) * 2;
                    float bv0 = __ldg(be + (size_t)e * OO + n0);
                    float bv1 = __ldg(be + (size_t)e * OO + n0 + 1);
                    oacc[mi][j][0] = fmaf(g0, gelu_exact(hacc[mi][j][0] + bv0), oacc[mi][j][0]);
                    oacc[mi][j][1] = fmaf(g0, gelu_exact(hacc[mi][j][1] + bv1), oacc[mi][j][1]);
                    oacc[mi][j][2] = fmaf(g1, gelu_exact(hacc[mi][j][2] + bv0), oacc[mi][j][2]);
                    oacc[mi][j][3] = fmaf(g1, gelu_exact(hacc[mi][j][3] + bv1), oacc[mi][j][3]);
                }
            }
        }

        // ---- store ----
        #pragma unroll
        for (int mi = 0; mi < 2; mi++) {
            int row = token0 + wm * 32 + mi * 16 + (lane >> 2);
            #pragma unroll
            for (int j = 0; j < 4; j++) {
                int n = col0 + wn * 32 + j * 8 + (lane & 3) * 2;
                float2 v0 = make_float2(oacc[mi][j][0], oacc[mi][j][1]);
                float2 v1 = make_float2(oacc[mi][j][2], oacc[mi][j][3]);
                *reinterpret_cast<float2*>(out + (size_t)row * OO + n) = v0;
                *reinterpret_cast<float2*>(out + (size_t)(row + 8) * OO + n) = v1;
            }
        }
    }
}

// ---------------------------------------------------------------------------
// kernel_launch — graph-capturable, allocation-free.
// Inputs: x[4,4096,256] f32, We[16,256,256] f32, be[16,256] f32,
//         Wg[256,16] f32, bg[16] f32. Output: [4,4096,256] f32.
// ---------------------------------------------------------------------------
extern "C" void kernel_launch(void* const* d_in, const int* in_sizes, int n_in,
                              void* d_out, int out_size) {
    const float* x  = (const float*)d_in[0];
    const float* We = (const float*)d_in[1];
    const float* be = (const float*)d_in[2];
    const float* Wg = (const float*)d_in[3];
    const float* bg = (const float*)d_in[4];
    float* out = (float*)d_out;

    cudaFuncSetAttribute(moe_kernel,
                         cudaFuncAttributeMaxDynamicSharedMemorySize, SMEM_TOTAL);

    permute_we<<<1024, 256>>>(We);
    moe_kernel<<<(NTOK / TILE_M) * 2, NTHREADS, SMEM_TOTAL>>>(x, be, Wg, bg, out);
}